// round 7
// baseline (speedup 1.0000x reference)
#include <cuda_runtime.h>
#include <cuda_bf16.h>
#include <mma.h>

using namespace nvcuda;

#define NUM_C 2048
#define LEN_Q 32
#define D 640

// Scratch (no cudaMalloc allowed)
__device__ __nv_bfloat16 g_u_bf[NUM_C * D];   // u = s_b*v_b + k_b  (bf16)
__device__ __nv_bfloat16 g_w_bf[D * D];       // W in bf16
__device__ __nv_bfloat16 g_yg[NUM_C * D];     // yg = (W u + b_fc)*gamma1 (bf16)

#define WCONV_BLOCKS 400   // (640*640/4)/256
#define PREP_BLOCKS  256   // 2048 batches / 8 per block (warp per batch)

// ---------------------------------------------------------------------------
// K1 (R4-proven): [0..399] W fp32->bf16 ; [400..655] u prep warp-per-batch
// ---------------------------------------------------------------------------
__global__ __launch_bounds__(256) void k_prep(const float* __restrict__ W,
                                              const float* __restrict__ v,
                                              const float* __restrict__ k) {
    const int t = threadIdx.x;
    if (blockIdx.x < WCONV_BLOCKS) {
        const int i4 = blockIdx.x * 256 + t;
        const float4 w = ((const float4*)W)[i4];
        __nv_bfloat162 p0 = __floats2bfloat162_rn(w.x, w.y);
        __nv_bfloat162 p1 = __floats2bfloat162_rn(w.z, w.w);
        uint2 pk; pk.x = *(unsigned*)&p0; pk.y = *(unsigned*)&p1;
        ((uint2*)g_w_bf)[i4] = pk;
        return;
    }
    const int b    = (blockIdx.x - WCONV_BLOCKS) * 8 + (t >> 5);
    const int lane = t & 31;
    const float4* vp = (const float4*)(v + b * D);
    const float4* kp = (const float4*)(k + b * D);

    float4 vv[5], kk[5];
    float s = 0.f;
    #pragma unroll
    for (int j = 0; j < 5; j++) {
        vv[j] = vp[lane + j * 32];
        kk[j] = kp[lane + j * 32];
        s += vv[j].x + vv[j].y + vv[j].z + vv[j].w;
    }
    #pragma unroll
    for (int off = 16; off > 0; off >>= 1) s += __shfl_xor_sync(~0u, s, off);

    uint2* up = (uint2*)(g_u_bf + b * D);
    #pragma unroll
    for (int j = 0; j < 5; j++) {
        __nv_bfloat162 p0 = __floats2bfloat162_rn(fmaf(s, vv[j].x, kk[j].x),
                                                  fmaf(s, vv[j].y, kk[j].y));
        __nv_bfloat162 p1 = __floats2bfloat162_rn(fmaf(s, vv[j].z, kk[j].z),
                                                  fmaf(s, vv[j].w, kk[j].w));
        uint2 pk; pk.x = *(unsigned*)&p0; pk.y = *(unsigned*)&p1;
        up[lane + j * 32] = pk;
    }
}

// ---------------------------------------------------------------------------
// K2 (R4-proven): bf16 wmma GEMM, cp.async double-buffered.
// ---------------------------------------------------------------------------
#define GK_PAD 72   // 64 + 8 bf16 pad

__device__ __forceinline__ void cp_async16(void* smem_dst, const void* gmem_src) {
    unsigned s = (unsigned)__cvta_generic_to_shared(smem_dst);
    asm volatile("cp.async.ca.shared.global [%0], [%1], 16;\n" :: "r"(s), "l"(gmem_src));
}

__global__ __launch_bounds__(128) void k_gemm(const float* __restrict__ bfc,
                                              const float* __restrict__ gam) {
    __shared__ __align__(16) __nv_bfloat16 As[2][64 * GK_PAD];
    __shared__ __align__(16) __nv_bfloat16 Bs[2][64 * GK_PAD];
    __shared__ __align__(16) float Sout[64 * 64];

    const int bm = blockIdx.y * 64;
    const int bn = blockIdx.x * 64;
    const int tid = threadIdx.x;
    const int w  = tid >> 5;
    const int wm_l = (w >> 1) * 32;
    const int wn_l = (w & 1) * 32;

    auto prefetch = [&](int st, int k0) {
        #pragma unroll
        for (int i = 0; i < 4; i++) {
            const int e = tid + i * 128;
            const int r = e >> 3;
            const int c = (e & 7) * 8;
            cp_async16(&As[st][r * GK_PAD + c], &g_u_bf[(bm + r) * D + k0 + c]);
            cp_async16(&Bs[st][r * GK_PAD + c], &g_w_bf[(bn + r) * D + k0 + c]);
        }
        asm volatile("cp.async.commit_group;\n");
    };

    wmma::fragment<wmma::accumulator, 16, 16, 16, float> acc[2][2];
    #pragma unroll
    for (int i = 0; i < 2; i++)
        #pragma unroll
        for (int j = 0; j < 2; j++) wmma::fill_fragment(acc[i][j], 0.0f);

    prefetch(0, 0);

    #pragma unroll 1
    for (int kt = 0; kt < 10; kt++) {
        if (kt + 1 < 10) {
            prefetch((kt + 1) & 1, (kt + 1) * 64);
            asm volatile("cp.async.wait_group 1;\n");
        } else {
            asm volatile("cp.async.wait_group 0;\n");
        }
        __syncthreads();

        const int st = kt & 1;
        #pragma unroll
        for (int kk = 0; kk < 4; kk++) {
            wmma::fragment<wmma::matrix_a, 16, 16, 16, __nv_bfloat16, wmma::row_major> a[2];
            wmma::fragment<wmma::matrix_b, 16, 16, 16, __nv_bfloat16, wmma::col_major> bb[2];
            #pragma unroll
            for (int i = 0; i < 2; i++)
                wmma::load_matrix_sync(a[i], &As[st][(wm_l + i * 16) * GK_PAD + kk * 16], GK_PAD);
            #pragma unroll
            for (int j = 0; j < 2; j++)
                wmma::load_matrix_sync(bb[j], &Bs[st][(wn_l + j * 16) * GK_PAD + kk * 16], GK_PAD);
            #pragma unroll
            for (int i = 0; i < 2; i++)
                #pragma unroll
                for (int j = 0; j < 2; j++)
                    wmma::mma_sync(acc[i][j], a[i], bb[j], acc[i][j]);
        }
        __syncthreads();
    }

    #pragma unroll
    for (int i = 0; i < 2; i++)
        #pragma unroll
        for (int j = 0; j < 2; j++)
            wmma::store_matrix_sync(&Sout[(wm_l + i * 16) * 64 + wn_l + j * 16],
                                    acc[i][j], 64, wmma::mem_row_major);
    __syncthreads();

    #pragma unroll
    for (int i = 0; i < 16; i++) {
        const int e   = tid + i * 128;
        const int r   = e >> 5;
        const int cp  = e & 31;
        const int col = bn + cp * 2;
        const float x0 = (Sout[r * 64 + cp * 2 + 0] + __ldg(&bfc[col + 0])) * __ldg(&gam[col + 0]);
        const float x1 = (Sout[r * 64 + cp * 2 + 1] + __ldg(&bfc[col + 1])) * __ldg(&gam[col + 1]);
        *(__nv_bfloat162*)&g_yg[(bm + r) * D + col] = __floats2bfloat162_rn(x0, x1);
    }
}

// ---------------------------------------------------------------------------
// K3: LayerNorm. ONE BLOCK PER BATCH (2048 blocks, 512 thr).
// Stage yg/lnw/lnb once (13 MB total L2 vs 51 MB in R4, 80+ MB in R6).
// One __syncthreads; then 16 warps x 2 rows each, warp-local reductions only.
// ---------------------------------------------------------------------------
__global__ __launch_bounds__(512) void k_ln(const float* __restrict__ q,
                                            const float* __restrict__ lnw,
                                            const float* __restrict__ lnb,
                                            float* __restrict__ out) {
    const int b = blockIdx.x;
    __shared__ __align__(16) float s_yg[D];
    __shared__ __align__(16) float s_w[D];
    __shared__ __align__(16) float s_b[D];

    // one-shot staging: t<160 -> yg (uint2=4 bf16 -> float4), 160..319 -> lnw, 320..479 -> lnb
    {
        const int t = threadIdx.x;
        if (t < 160) {
            const uint2 p = ((const uint2*)(g_yg + b * D))[t];
            const float2 f0 = __bfloat1622float2(*(const __nv_bfloat162*)&p.x);
            const float2 f1 = __bfloat1622float2(*(const __nv_bfloat162*)&p.y);
            ((float4*)s_yg)[t] = make_float4(f0.x, f0.y, f1.x, f1.y);
        } else if (t < 320) {
            ((float4*)s_w)[t - 160] = ((const float4*)lnw)[t - 160];
        } else if (t < 480) {
            ((float4*)s_b)[t - 320] = ((const float4*)lnb)[t - 320];
        }
    }
    __syncthreads();

    const int warp = threadIdx.x >> 5;   // 0..15
    const int lane = threadIdx.x & 31;
    const float inv_d = 1.0f / (float)D;

    #pragma unroll
    for (int r = 0; r < 2; r++) {
        const long row = (long)b * LEN_Q + warp * 2 + r;
        const float4* qrow = (const float4*)(q + row * D);
        float4* orow       = (float4*)(out + row * D);

        float4 qv[5];
        #pragma unroll
        for (int j = 0; j < 5; j++) qv[j] = __ldcs(&qrow[j * 32 + lane]);

        float z[20];
        float sum = 0.f, sq = 0.f;
        #pragma unroll
        for (int j = 0; j < 5; j++) {
            const float4 yv = *(const float4*)(s_yg + (j * 32 + lane) * 4);
            const float z0 = qv[j].x + yv.x;
            const float z1 = qv[j].y + yv.y;
            const float z2 = qv[j].z + yv.z;
            const float z3 = qv[j].w + yv.w;
            z[j * 4 + 0] = z0; z[j * 4 + 1] = z1;
            z[j * 4 + 2] = z2; z[j * 4 + 3] = z3;
            sum += z0 + z1 + z2 + z3;
            sq = fmaf(z0, z0, sq); sq = fmaf(z1, z1, sq);
            sq = fmaf(z2, z2, sq); sq = fmaf(z3, z3, sq);
        }
        #pragma unroll
        for (int off = 16; off > 0; off >>= 1) {
            sum += __shfl_xor_sync(~0u, sum, off);
            sq  += __shfl_xor_sync(~0u, sq,  off);
        }
        const float mean = sum * inv_d;
        const float var  = sq * inv_d - mean * mean;
        const float rstd = rsqrtf(var + 1e-5f);

        #pragma unroll
        for (int j = 0; j < 5; j++) {
            const int c4 = j * 32 + lane;
            const int c  = c4 * 4;
            float4 o;
            o.x = (z[j * 4 + 0] - mean) * rstd * s_w[c + 0] + s_b[c + 0];
            o.y = (z[j * 4 + 1] - mean) * rstd * s_w[c + 1] + s_b[c + 1];
            o.z = (z[j * 4 + 2] - mean) * rstd * s_w[c + 2] + s_b[c + 2];
            o.w = (z[j * 4 + 3] - mean) * rstd * s_w[c + 3] + s_b[c + 3];
            __stcs(&orow[c4], o);
        }
    }
}

// ---------------------------------------------------------------------------
// Inputs: 0=q 1=k 2=v 3=w_fc 4=b_fc 5=gamma1 6=ln_w 7=ln_b
// ---------------------------------------------------------------------------
extern "C" void kernel_launch(void* const* d_in, const int* in_sizes, int n_in,
                              void* d_out, int out_size) {
    const float* q     = (const float*)d_in[0];
    const float* k     = (const float*)d_in[1];
    const float* v     = (const float*)d_in[2];
    const float* w_fc  = (const float*)d_in[3];
    const float* b_fc  = (const float*)d_in[4];
    const float* gam   = (const float*)d_in[5];
    const float* ln_w  = (const float*)d_in[6];
    const float* ln_b  = (const float*)d_in[7];
    float* out = (float*)d_out;

    k_prep<<<WCONV_BLOCKS + PREP_BLOCKS, 256>>>(w_fc, v, k);
    k_gemm<<<dim3(D / 64, NUM_C / 64), 128>>>(b_fc, gam);
    k_ln<<<NUM_C, 512>>>(q, ln_w, ln_b, out);
}

// round 8
// speedup vs baseline: 1.3813x; 1.3813x over previous
#include <cuda_runtime.h>
#include <cuda_bf16.h>
#include <mma.h>

using namespace nvcuda;

#define NUM_C 2048
#define LEN_Q 32
#define D 640

// Scratch (no cudaMalloc allowed)
__device__ __nv_bfloat16 g_u_bf[NUM_C * D];   // u = s_b*v_b + k_b  (bf16)
__device__ __nv_bfloat16 g_w_bf[D * D];       // W in bf16
__device__ __nv_bfloat16 g_yg[NUM_C * D];     // yg = (W u + b_fc)*gamma1 (bf16)

#define WCONV_BLOCKS 400   // (640*640/4)/256

// ---------------------------------------------------------------------------
// K1 (R3-proven shape): [0..399] W fp32->bf16 ; [400..2447] block-per-batch u prep
// ---------------------------------------------------------------------------
__global__ __launch_bounds__(256) void k_prep(const float* __restrict__ W,
                                              const float* __restrict__ v,
                                              const float* __restrict__ k) {
    const int t = threadIdx.x;
    if (blockIdx.x < WCONV_BLOCKS) {
        const int i4 = blockIdx.x * 256 + t;
        const float4 w = ((const float4*)W)[i4];
        __nv_bfloat162 p0 = __floats2bfloat162_rn(w.x, w.y);
        __nv_bfloat162 p1 = __floats2bfloat162_rn(w.z, w.w);
        uint2 pk; pk.x = *(unsigned*)&p0; pk.y = *(unsigned*)&p1;
        ((uint2*)g_w_bf)[i4] = pk;
        return;
    }
    const int b = blockIdx.x - WCONV_BLOCKS;
    __shared__ float red[5];
    float4 v4, k4;
    if (t < 160) {
        v4 = ((const float4*)(v + b * D))[t];
        k4 = ((const float4*)(k + b * D))[t];
        float s = v4.x + v4.y + v4.z + v4.w;
        #pragma unroll
        for (int off = 16; off > 0; off >>= 1) s += __shfl_xor_sync(0xffffffffu, s, off);
        if ((t & 31) == 0) red[t >> 5] = s;
    }
    __syncthreads();
    if (t < 160) {
        const float sb = red[0] + red[1] + red[2] + red[3] + red[4];
        __nv_bfloat162 p0 = __floats2bfloat162_rn(fmaf(sb, v4.x, k4.x), fmaf(sb, v4.y, k4.y));
        __nv_bfloat162 p1 = __floats2bfloat162_rn(fmaf(sb, v4.z, k4.z), fmaf(sb, v4.w, k4.w));
        uint2 pk; pk.x = *(unsigned*)&p0; pk.y = *(unsigned*)&p1;
        ((uint2*)(g_u_bf + b * D))[t] = pk;
    }
}

// ---------------------------------------------------------------------------
// K2 (R4-proven): bf16 wmma GEMM, cp.async double-buffered.
// ---------------------------------------------------------------------------
#define GK_PAD 72   // 64 + 8 bf16 pad

__device__ __forceinline__ void cp_async16(void* smem_dst, const void* gmem_src) {
    unsigned s = (unsigned)__cvta_generic_to_shared(smem_dst);
    asm volatile("cp.async.ca.shared.global [%0], [%1], 16;\n" :: "r"(s), "l"(gmem_src));
}

__global__ __launch_bounds__(128) void k_gemm(const float* __restrict__ bfc,
                                              const float* __restrict__ gam) {
    __shared__ __align__(16) __nv_bfloat16 As[2][64 * GK_PAD];
    __shared__ __align__(16) __nv_bfloat16 Bs[2][64 * GK_PAD];
    __shared__ __align__(16) float Sout[64 * 64];

    const int bm = blockIdx.y * 64;
    const int bn = blockIdx.x * 64;
    const int tid = threadIdx.x;
    const int w  = tid >> 5;
    const int wm_l = (w >> 1) * 32;
    const int wn_l = (w & 1) * 32;

    auto prefetch = [&](int st, int k0) {
        #pragma unroll
        for (int i = 0; i < 4; i++) {
            const int e = tid + i * 128;
            const int r = e >> 3;
            const int c = (e & 7) * 8;
            cp_async16(&As[st][r * GK_PAD + c], &g_u_bf[(bm + r) * D + k0 + c]);
            cp_async16(&Bs[st][r * GK_PAD + c], &g_w_bf[(bn + r) * D + k0 + c]);
        }
        asm volatile("cp.async.commit_group;\n");
    };

    wmma::fragment<wmma::accumulator, 16, 16, 16, float> acc[2][2];
    #pragma unroll
    for (int i = 0; i < 2; i++)
        #pragma unroll
        for (int j = 0; j < 2; j++) wmma::fill_fragment(acc[i][j], 0.0f);

    prefetch(0, 0);

    #pragma unroll 1
    for (int kt = 0; kt < 10; kt++) {
        if (kt + 1 < 10) {
            prefetch((kt + 1) & 1, (kt + 1) * 64);
            asm volatile("cp.async.wait_group 1;\n");
        } else {
            asm volatile("cp.async.wait_group 0;\n");
        }
        __syncthreads();

        const int st = kt & 1;
        #pragma unroll
        for (int kk = 0; kk < 4; kk++) {
            wmma::fragment<wmma::matrix_a, 16, 16, 16, __nv_bfloat16, wmma::row_major> a[2];
            wmma::fragment<wmma::matrix_b, 16, 16, 16, __nv_bfloat16, wmma::col_major> bb[2];
            #pragma unroll
            for (int i = 0; i < 2; i++)
                wmma::load_matrix_sync(a[i], &As[st][(wm_l + i * 16) * GK_PAD + kk * 16], GK_PAD);
            #pragma unroll
            for (int j = 0; j < 2; j++)
                wmma::load_matrix_sync(bb[j], &Bs[st][(wn_l + j * 16) * GK_PAD + kk * 16], GK_PAD);
            #pragma unroll
            for (int i = 0; i < 2; i++)
                #pragma unroll
                for (int j = 0; j < 2; j++)
                    wmma::mma_sync(acc[i][j], a[i], bb[j], acc[i][j]);
        }
        __syncthreads();
    }

    #pragma unroll
    for (int i = 0; i < 2; i++)
        #pragma unroll
        for (int j = 0; j < 2; j++)
            wmma::store_matrix_sync(&Sout[(wm_l + i * 16) * 64 + wn_l + j * 16],
                                    acc[i][j], 64, wmma::mem_row_major);
    __syncthreads();

    #pragma unroll
    for (int i = 0; i < 16; i++) {
        const int e   = tid + i * 128;
        const int r   = e >> 5;
        const int cp  = e & 31;
        const int col = bn + cp * 2;
        const float x0 = (Sout[r * 64 + cp * 2 + 0] + __ldg(&bfc[col + 0])) * __ldg(&gam[col + 0]);
        const float x1 = (Sout[r * 64 + cp * 2 + 1] + __ldg(&bfc[col + 1])) * __ldg(&gam[col + 1]);
        *(__nv_bfloat162*)&g_yg[(bm + r) * D + col] = __floats2bfloat162_rn(x0, x1);
    }
}

// ---------------------------------------------------------------------------
// K3: LayerNorm. 512 thr = 16 warps = 16 CONCURRENT rows; 2 blocks/batch.
// One-shot staging (<=1 load/thread), ONE syncthreads, then pure warp-local:
// 5 x LDG.128(ldcs) in flight -> reduce -> 5 x STG.128(stcs).
// Low regs: only qv kept; z recomputed from smem in write pass.
// ---------------------------------------------------------------------------
__global__ __launch_bounds__(512) void k_ln(const float* __restrict__ q,
                                            const float* __restrict__ lnw,
                                            const float* __restrict__ lnb,
                                            float* __restrict__ out) {
    const int b       = blockIdx.x >> 1;
    const int rowbase = (blockIdx.x & 1) * 16;

    __shared__ __align__(16) float s_yg[D];
    __shared__ __align__(16) float s_w[D];
    __shared__ __align__(16) float s_b[D];

    {
        const int t = threadIdx.x;
        if (t < 160) {
            const uint2 p = ((const uint2*)(g_yg + b * D))[t];
            const float2 f0 = __bfloat1622float2(*(const __nv_bfloat162*)&p.x);
            const float2 f1 = __bfloat1622float2(*(const __nv_bfloat162*)&p.y);
            ((float4*)s_yg)[t] = make_float4(f0.x, f0.y, f1.x, f1.y);
        } else if (t < 320) {
            ((float4*)s_w)[t - 160] = ((const float4*)lnw)[t - 160];
        } else if (t < 480) {
            ((float4*)s_b)[t - 320] = ((const float4*)lnb)[t - 320];
        }
    }
    __syncthreads();

    const int warp = threadIdx.x >> 5;   // 0..15 -> row
    const int lane = threadIdx.x & 31;
    const long row = (long)b * LEN_Q + rowbase + warp;
    const float4* qrow = (const float4*)(q + row * D);
    float4* orow       = (float4*)(out + row * D);

    float4 qv[5];
    #pragma unroll
    for (int j = 0; j < 5; j++) qv[j] = __ldcs(&qrow[j * 32 + lane]);

    float sum = 0.f, sq = 0.f;
    #pragma unroll
    for (int j = 0; j < 5; j++) {
        const float4 yv = *(const float4*)(s_yg + (j * 32 + lane) * 4);
        const float z0 = qv[j].x + yv.x;
        const float z1 = qv[j].y + yv.y;
        const float z2 = qv[j].z + yv.z;
        const float z3 = qv[j].w + yv.w;
        sum += z0 + z1 + z2 + z3;
        sq = fmaf(z0, z0, sq); sq = fmaf(z1, z1, sq);
        sq = fmaf(z2, z2, sq); sq = fmaf(z3, z3, sq);
    }
    #pragma unroll
    for (int off = 16; off > 0; off >>= 1) {
        sum += __shfl_xor_sync(~0u, sum, off);
        sq  += __shfl_xor_sync(~0u, sq,  off);
    }
    const float inv_d = 1.0f / (float)D;
    const float mean = sum * inv_d;
    const float var  = sq * inv_d - mean * mean;
    const float rstd = rsqrtf(var + 1e-5f);

    #pragma unroll
    for (int j = 0; j < 5; j++) {
        const int c4 = j * 32 + lane;
        const int c  = c4 * 4;
        const float4 yv = *(const float4*)(s_yg + c);
        float4 o;
        o.x = (qv[j].x + yv.x - mean) * rstd * s_w[c + 0] + s_b[c + 0];
        o.y = (qv[j].y + yv.y - mean) * rstd * s_w[c + 1] + s_b[c + 1];
        o.z = (qv[j].z + yv.z - mean) * rstd * s_w[c + 2] + s_b[c + 2];
        o.w = (qv[j].w + yv.w - mean) * rstd * s_w[c + 3] + s_b[c + 3];
        __stcs(&orow[c4], o);
    }
}

// ---------------------------------------------------------------------------
// Inputs: 0=q 1=k 2=v 3=w_fc 4=b_fc 5=gamma1 6=ln_w 7=ln_b
// ---------------------------------------------------------------------------
extern "C" void kernel_launch(void* const* d_in, const int* in_sizes, int n_in,
                              void* d_out, int out_size) {
    const float* q     = (const float*)d_in[0];
    const float* k     = (const float*)d_in[1];
    const float* v     = (const float*)d_in[2];
    const float* w_fc  = (const float*)d_in[3];
    const float* b_fc  = (const float*)d_in[4];
    const float* gam   = (const float*)d_in[5];
    const float* ln_w  = (const float*)d_in[6];
    const float* ln_b  = (const float*)d_in[7];
    float* out = (float*)d_out;

    k_prep<<<WCONV_BLOCKS + NUM_C, 256>>>(w_fc, v, k);
    k_gemm<<<dim3(D / 64, NUM_C / 64), 128>>>(b_fc, gam);
    k_ln<<<NUM_C * 2, 512>>>(q, ln_w, ln_b, out);
}